// round 16
// baseline (speedup 1.0000x reference)
#include <cuda_runtime.h>
#include <cstdint>
#include <cstddef>

// ---------------------------------------------------------------------------
// PolicyHead round 15 (= round 14 with attf phase-1 B-frags via LDG from L2):
//   logits = out@M@out^T + u.out_i + v.out_j + s0,  M = W2^T W3 (precomputed)
//   attf v6: no Mt smem staging at all — B fragments LDG.64 direct from g_mt
//   (L2-hot, rows pre-perm'd), register double-buffered. Zero phase-1 syncs.
// ---------------------------------------------------------------------------

#define HDIM 256
#define MROWS 262144
#define PSCALE 0.0625f

__device__ unsigned g_out[(size_t)MROWS * HDIM];
__device__ unsigned g_w1[HDIM * HDIM];     // tf32 bits, perm'd k
__device__ unsigned g_mt[HDIM * HDIM];     // Mt[c,a], tf32, perm on a
__device__ float    g_u[HDIM];             // perm-indexed
__device__ float    g_v[HDIM];             // perm-indexed
__device__ float    g_wp[4 * HDIM];        // perm-indexed
__device__ float    g_misc[8];             // [0]=s0, [1..4]=d0[p]

__device__ __forceinline__ unsigned f2tf(float f) {
    unsigned r;
    asm("cvt.rna.tf32.f32 %0, %1;" : "=r"(r) : "f"(f));
    return r;
}
__device__ __forceinline__ int perm(int c) {
    return (c & ~7) | ((c & 3) << 1) | ((c >> 2) & 1);
}
__device__ __forceinline__ void mma8(float* d, const unsigned* a, const unsigned* b) {
    asm volatile(
        "mma.sync.aligned.m16n8k8.row.col.f32.tf32.tf32.f32 "
        "{%0,%1,%2,%3}, {%4,%5,%6,%7}, {%8,%9}, {%0,%1,%2,%3};\n"
        : "+f"(d[0]), "+f"(d[1]), "+f"(d[2]), "+f"(d[3])
        : "r"(a[0]), "r"(a[1]), "r"(a[2]), "r"(a[3]), "r"(b[0]), "r"(b[1]));
}
__device__ __forceinline__ unsigned sptr(const void* p) {
    return (unsigned)__cvta_generic_to_shared(p);
}
__device__ __forceinline__ void cpa16(unsigned s, const void* g) {
    asm volatile("cp.async.ca.shared.global [%0], [%1], 16;" :: "r"(s), "l"(g));
}
#define CPA_COMMIT asm volatile("cp.async.commit_group;")
#define CPA_WAIT(n) asm volatile("cp.async.wait_group %0;" :: "n"(n))

// ---------------------------------------------------------------------------
__global__ void prep_w1_kernel(const float* __restrict__ w1) {
    int i = blockIdx.x * 256 + threadIdx.x;
    int row = i >> 8, col = i & 255;
    g_w1[row * HDIM + perm(col)] = f2tf(w1[i]);
}

__global__ __launch_bounds__(256)
void prepM_kernel(const float* __restrict__ w2, const float* __restrict__ w3) {
    extern __shared__ float s[];
    float* s2 = s;               // [256][68]
    float* s3 = s + 256 * 68;
    const int a0 = (blockIdx.x & 3) * 64, c0 = (blockIdx.x >> 2) * 64;
    const int tid = threadIdx.x;
    for (int j = tid; j < 256 * 16; j += 256) {
        int h = j >> 4, q4 = (j & 15) << 2;
        *(float4*)&s2[h * 68 + q4] = *(const float4*)(w2 + h * HDIM + a0 + q4);
        *(float4*)&s3[h * 68 + q4] = *(const float4*)(w3 + h * HDIM + c0 + q4);
    }
    __syncthreads();
    const int tx = tid & 15, ty = tid >> 4;
    float acc[4][4] = {};
    for (int h = 0; h < 256; h++) {
        float4 av = *(float4*)&s2[h * 68 + tx * 4];
        float4 cv = *(float4*)&s3[h * 68 + ty * 4];
        float aa[4] = {av.x, av.y, av.z, av.w};
        float cc[4] = {cv.x, cv.y, cv.z, cv.w};
#pragma unroll
        for (int i = 0; i < 4; i++)
#pragma unroll
            for (int j = 0; j < 4; j++) acc[i][j] += cc[i] * aa[j];
    }
#pragma unroll
    for (int i = 0; i < 4; i++)
#pragma unroll
        for (int j = 0; j < 4; j++)
            g_mt[(c0 + ty * 4 + i) * HDIM + perm(a0 + tx * 4 + j)] = f2tf(acc[i][j]);
}

__global__ void prepv_kernel(const float* __restrict__ w2, const float* __restrict__ b2,
                             const float* __restrict__ w3, const float* __restrict__ b3,
                             const float* __restrict__ w4) {
    int a = threadIdx.x;
    float u = 0.f, v = 0.f, p0 = 0.f, p1 = 0.f, p2 = 0.f, p3 = 0.f;
    for (int h = 0; h < 256; h++) {
        float w2v = w2[h * HDIM + a], w3v = w3[h * HDIM + a];
        u += w2v * b3[h];
        v += b2[h] * w3v;
        p0 += w3v * w4[0 * HDIM + h];
        p1 += w3v * w4[1 * HDIM + h];
        p2 += w3v * w4[2 * HDIM + h];
        p3 += w3v * w4[3 * HDIM + h];
    }
    int pa = perm(a);
    g_u[pa] = u; g_v[pa] = v;
    g_wp[0 * HDIM + pa] = p0; g_wp[1 * HDIM + pa] = p1;
    g_wp[2 * HDIM + pa] = p2; g_wp[3 * HDIM + pa] = p3;
    if (a == 0) {
        float s = 0.f;
        for (int h = 0; h < 256; h++) s += b2[h] * b3[h];
        g_misc[0] = s;
    }
    if (a >= 1 && a <= 4) {
        float d = 0.f;
        for (int h = 0; h < 256; h++) d += b3[h] * w4[(a - 1) * HDIM + h];
        g_misc[a] = d;
    }
}

// ---------------------------------------------------------------------------
// GEMM1 (round-5, proven 255us): out = relu(x @ W1^T + b1).
// ---------------------------------------------------------------------------
constexpr int GSA = 36;
constexpr int GSB = 40;

__global__ __launch_bounds__(256, 2)
void gemm1_kernel(const float* __restrict__ A, const float* __restrict__ bias,
                  unsigned* __restrict__ C) {
    extern __shared__ unsigned sh[];
    unsigned* sA = sh;
    unsigned* sB = sh + 2 * 128 * GSA;
    const int m0 = blockIdx.y * 128, n0 = blockIdx.x * 128;
    const int tid = threadIdx.x;
    const int warp = tid >> 5, lane = tid & 31, g = lane >> 2, t = lane & 3;
    const int wm = warp >> 1, wn = warp & 1;

    float acc[2][8][4];
#pragma unroll
    for (int i = 0; i < 2; i++)
#pragma unroll
        for (int j = 0; j < 8; j++)
#pragma unroll
            for (int l = 0; l < 4; l++) acc[i][j][l] = 0.f;

    const int lrow = tid >> 3, lc4 = (tid & 7) << 2;

#pragma unroll
    for (int i = 0; i < 4; i++) {
        int row = lrow + i * 32;
        cpa16(sptr(&sA[row * GSA + lc4]), A + (size_t)(m0 + row) * HDIM + lc4);
        cpa16(sptr(&sB[row * GSB + lc4]), g_w1 + (size_t)(n0 + row) * HDIM + lc4);
    }
    CPA_COMMIT;

    for (int c = 0; c < 8; c++) {
        int cur = c & 1;
        if (c < 7) {
            int nx = cur ^ 1, k0 = (c + 1) * 32;
#pragma unroll
            for (int i = 0; i < 4; i++) {
                int row = lrow + i * 32;
                cpa16(sptr(&sA[nx * 128 * GSA + row * GSA + lc4]),
                      A + (size_t)(m0 + row) * HDIM + k0 + lc4);
                cpa16(sptr(&sB[nx * 128 * GSB + row * GSB + lc4]),
                      g_w1 + (size_t)(n0 + row) * HDIM + k0 + lc4);
            }
            CPA_COMMIT;
            CPA_WAIT(1);
        } else {
            CPA_WAIT(0);
        }
        __syncthreads();
        const unsigned* As = &sA[cur * 128 * GSA];
        const unsigned* Bs = &sB[cur * 128 * GSB];
#pragma unroll
        for (int ks = 0; ks < 32; ks += 8) {
            unsigned a[2][4];
#pragma unroll
            for (int mi = 0; mi < 2; mi++) {
                int r = wm * 32 + mi * 16;
                a[mi][0] = f2tf(__uint_as_float(As[(r + g) * GSA + ks + t]));
                a[mi][1] = f2tf(__uint_as_float(As[(r + g + 8) * GSA + ks + t]));
                a[mi][2] = f2tf(__uint_as_float(As[(r + g) * GSA + ks + t + 4]));
                a[mi][3] = f2tf(__uint_as_float(As[(r + g + 8) * GSA + ks + t + 4]));
            }
#pragma unroll
            for (int ni = 0; ni < 8; ni++) {
                int cc = wn * 64 + ni * 8;
                uint2 bv = *(const uint2*)&Bs[(cc + g) * GSB + ks + 2 * t];
                unsigned bb[2] = {bv.x, bv.y};
                mma8(acc[0][ni], a[0], bb);
                mma8(acc[1][ni], a[1], bb);
            }
        }
        __syncthreads();
    }
#pragma unroll
    for (int mi = 0; mi < 2; mi++)
#pragma unroll
        for (int h = 0; h < 2; h++) {
            int r = m0 + wm * 32 + mi * 16 + g + h * 8;
#pragma unroll
            for (int ni = 0; ni < 8; ni++) {
                int cc = n0 + wn * 64 + ni * 8 + 2 * t;
                float v0 = fmaxf(acc[mi][ni][h * 2 + 0] + bias[cc], 0.f);
                float v1 = fmaxf(acc[mi][ni][h * 2 + 1] + bias[cc + 1], 0.f);
                C[(size_t)r * HDIM + perm(cc)]     = f2tf(v0);
                C[(size_t)r * HDIM + perm(cc + 1)] = f2tf(v1);
            }
        }
}

// ---------------------------------------------------------------------------
// attf v6: phase-1 B-frags direct LDG.64 from g_mt (L2-hot), register
// double-buffered; NO Mt smem staging, zero phase-1 syncs.
// smem: outs[64x256 packed swz] | qtmp[64x64] | misc. 82.5KB -> 2 CTAs/SM.
// ---------------------------------------------------------------------------
constexpr int A6_QTMP  = 16384;       // 64*64 words
constexpr int A6_MISC  = 20480;       // uo64 + vo64 + offs32 = 160
constexpr int A6_WORDS = 20640;       // 82560 bytes

__global__ __launch_bounds__(256, 2)
void attf_kernel(const int* __restrict__ gidx, float* __restrict__ out) {
    extern __shared__ unsigned sh[];
    unsigned* outs = sh;
    unsigned* qtmp = sh + A6_QTMP;
    float* uo   = (float*)(sh + A6_MISC);
    float* vo   = uo + 64;
    float* offs = vo + 64;
    float* fulls = (float*)sh;               // alias outs (dead after reads)

    const int b = blockIdx.x, tid = threadIdx.x;
    const unsigned* ob = g_out + (size_t)b * 64 * HDIM;

    // prologue: outs (packed+swizzled)
#pragma unroll
    for (int i = 0; i < 16; i++) {
        int idx = tid + i * 256;
        int row = idx >> 6, c4 = (idx & 63) << 2;
        cpa16(sptr(&outs[row * 256 + (c4 ^ ((row & 3) << 3))]),
              ob + (size_t)row * HDIM + c4);
    }
    CPA_COMMIT;

    const int warp = tid >> 5, lane = tid & 31, g = lane >> 2, t = lane & 3;
    const int sw = (g & 3) << 3;
    const int wm = warp >> 2, wn = warp & 3;     // phase 1: 32x64 tiles
    const int wm2 = warp >> 1, wn2 = warp & 1;   // phase 2: 16x32 tiles

    float acc[2][8][4];
#pragma unroll
    for (int i = 0; i < 2; i++)
#pragma unroll
        for (int j = 0; j < 8; j++)
#pragma unroll
            for (int l = 0; l < 4; l++) acc[i][j][l] = 0.f;

    // per-warp Mt base rows: c = wn*64 + ni*8 + g
    const unsigned* mtw = g_mt + (size_t)(wn * 64 + g) * HDIM + 2 * t;

    CPA_WAIT(0);
    __syncthreads();      // outs resident

    // ---- phase 1: tmp = outs @ Mt^T; B-frags LDG.64, reg double-buffer ----
    uint2 bcur[8];
#pragma unroll
    for (int ni = 0; ni < 8; ni++)
        bcur[ni] = *(const uint2*)(mtw + (size_t)ni * 8 * HDIM);

    for (int step = 0; step < 32; step++) {
        const int kb = step * 8;
        uint2 bnext[8];
        if (step < 31) {
#pragma unroll
            for (int ni = 0; ni < 8; ni++)
                bnext[ni] = *(const uint2*)(mtw + (size_t)ni * 8 * HDIM + kb + 8);
        }
        unsigned a[2][4];
#pragma unroll
        for (int mi = 0; mi < 2; mi++) {
            int r0 = wm * 32 + mi * 16 + g;
            uint2 a0 = *(const uint2*)&outs[r0 * 256 + ((kb + 2 * t) ^ sw)];
            uint2 a1 = *(const uint2*)&outs[(r0 + 8) * 256 + ((kb + 2 * t) ^ sw)];
            a[mi][0] = a0.x; a[mi][1] = a1.x; a[mi][2] = a0.y; a[mi][3] = a1.y;
        }
#pragma unroll
        for (int ni = 0; ni < 8; ni++) {
            unsigned bb[2] = {bcur[ni].x, bcur[ni].y};
            mma8(acc[0][ni], a[0], bb);
            mma8(acc[1][ni], a[1], bb);
        }
        if (step < 31) {
#pragma unroll
            for (int ni = 0; ni < 8; ni++) bcur[ni] = bnext[ni];
        }
    }

    // ---- phase 2: logits = tmp @ outs^T via 4 q-passes through qtmp ----
    float acc2[4][4];
#pragma unroll
    for (int i = 0; i < 4; i++)
#pragma unroll
        for (int j = 0; j < 4; j++) acc2[i][j] = 0.f;

    for (int q = 0; q < 4; q++) {
        __syncthreads();   // prior q reads complete (first: after phase 1)
        if (wn == q) {
#pragma unroll
            for (int mi = 0; mi < 2; mi++)
#pragma unroll
                for (int ni = 0; ni < 8; ni++) {
                    int lc = ni * 8 + 2 * t;
                    int lp0 = (lc & ~7) | ((lc & 3) << 1) | ((lc >> 2) & 1);
                    int lc1 = lc + 1;
                    int lp1 = (lc1 & ~7) | ((lc1 & 3) << 1) | ((lc1 >> 2) & 1);
                    int r = wm * 32 + mi * 16 + g;
                    qtmp[r * 64 + (lp0 ^ sw)]       = f2tf(acc[mi][ni][0]);
                    qtmp[r * 64 + (lp1 ^ sw)]       = f2tf(acc[mi][ni][1]);
                    qtmp[(r + 8) * 64 + (lp0 ^ sw)] = f2tf(acc[mi][ni][2]);
                    qtmp[(r + 8) * 64 + (lp1 ^ sw)] = f2tf(acc[mi][ni][3]);
                }
        }
        __syncthreads();
#pragma unroll
        for (int k8 = 0; k8 < 64; k8 += 8) {
            int r2 = wm2 * 16 + g;
            uint2 a0 = *(const uint2*)&qtmp[r2 * 64 + ((k8 + 2 * t) ^ sw)];
            uint2 a1 = *(const uint2*)&qtmp[(r2 + 8) * 64 + ((k8 + 2 * t) ^ sw)];
            unsigned a[4] = {a0.x, a1.x, a0.y, a1.y};
#pragma unroll
            for (int ni = 0; ni < 4; ni++) {
                int c = wn2 * 32 + ni * 8 + g;
                uint2 bv = *(const uint2*)&outs[c * 256 + ((q * 64 + k8 + 2 * t) ^ sw)];
                unsigned bb[2] = {bv.x, bv.y};
                mma8(acc2[ni], a, bb);
            }
        }
    }

    // ---- rank-1 terms: one row per warp, lane-striped (conflict-free) ----
    {
#pragma unroll
        for (int rr = 0; rr < 8; rr++) {
            int r = warp * 8 + rr;
            int swr = (r & 3) << 3;
            const unsigned* orow = &outs[r * 256];
            float su = 0.f, sv = 0.f;
#pragma unroll
            for (int j = 0; j < 8; j++) {
                int pp = lane + 32 * j;
                float ov = __uint_as_float(orow[pp ^ swr]);
                su += g_u[pp] * ov;
                sv += g_v[pp] * ov;
            }
#pragma unroll
            for (int d = 16; d > 0; d >>= 1) {
                su += __shfl_down_sync(0xffffffffu, su, d);
                sv += __shfl_down_sync(0xffffffffu, sv, d);
            }
            if (lane == 0) { uo[r] = su; vo[r] = sv; }
        }
    }
    {
        int s = warp;
        int r = 56 + s, swr = (r & 3) << 3;
        const unsigned* kr = &outs[r * 256];
#pragma unroll
        for (int p = 0; p < 4; p++) {
            const float* wr = g_wp + p * HDIM;
            float sum = 0.f;
#pragma unroll
            for (int j = 0; j < 8; j++) {
                int pp = lane + 32 * j;
                sum += __uint_as_float(kr[pp ^ swr]) * wr[pp];
            }
#pragma unroll
            for (int d = 16; d > 0; d >>= 1)
                sum += __shfl_down_sync(0xffffffffu, sum, d);
            if (lane == 0) offs[p * 8 + s] = sum + g_misc[1 + p];
        }
    }
    __syncthreads();   // all outs reads done -> fulls may overwrite

    const float s0v = g_misc[0];
#pragma unroll
    for (int ni = 0; ni < 4; ni++) {
        int cc = wn2 * 32 + ni * 8 + 2 * t;
        int r = wm2 * 16 + g;
        fulls[r * 64 + cc]           = (acc2[ni][0] + uo[r] + vo[cc] + s0v) * PSCALE;
        fulls[r * 64 + cc + 1]       = (acc2[ni][1] + uo[r] + vo[cc + 1] + s0v) * PSCALE;
        fulls[(r + 8) * 64 + cc]     = (acc2[ni][2] + uo[r + 8] + vo[cc] + s0v) * PSCALE;
        fulls[(r + 8) * 64 + cc + 1] = (acc2[ni][3] + uo[r + 8] + vo[cc + 1] + s0v) * PSCALE;
    }
    __syncthreads();

    if (tid < 192) {
        int qq = tid / 24, rr = tid % 24, s = rr / 3, p = rr % 3;
        fulls[4096 + tid] = offs[p * 8 + s] + offs[24 + s]
                          + fulls[(48 + qq) * 64 + 56 + s];
    }
    __syncthreads();

    float* obp = out + (size_t)b * 1858;
    for (int i = tid; i < 1858; i += 256) obp[i] = fulls[gidx[i]];
}

// ---------------------------------------------------------------------------
extern "C" void kernel_launch(void* const* d_in, const int* in_sizes, int n_in,
                              void* d_out, int out_size) {
    const float* x  = (const float*)d_in[0];
    const float* w1 = (const float*)d_in[1];
    const float* b1 = (const float*)d_in[2];
    const float* w2 = (const float*)d_in[3];
    const float* b2 = (const float*)d_in[4];
    const float* w3 = (const float*)d_in[5];
    const float* b3 = (const float*)d_in[6];
    const float* w4 = (const float*)d_in[7];
    const int*   gi = (const int*)d_in[8];
    float* out = (float*)d_out;

    const int M = in_sizes[0] / HDIM;     // 262144
    const int nblk = M / 64;              // 4096

    unsigned* o;
    cudaGetSymbolAddress((void**)&o, g_out);

    const int smemM = 2 * 256 * 68 * 4;                        // 139264
    const int smem1 = (2 * 128 * GSA + 2 * 128 * GSB) * 4;     // 77824
    const int smemA = A6_WORDS * 4;                            // 82560

    static bool init = false;
    if (!init) {
        cudaFuncSetAttribute((const void*)prepM_kernel,
                             cudaFuncAttributeMaxDynamicSharedMemorySize, smemM);
        cudaFuncSetAttribute((const void*)gemm1_kernel,
                             cudaFuncAttributeMaxDynamicSharedMemorySize, smem1);
        cudaFuncSetAttribute((const void*)attf_kernel,
                             cudaFuncAttributeMaxDynamicSharedMemorySize, smemA);
        init = true;
    }

    prep_w1_kernel<<<HDIM * HDIM / 256, 256>>>(w1);
    prepM_kernel<<<16, 256, smemM>>>(w2, w3);
    prepv_kernel<<<1, 256>>>(w2, b2, w3, b3, w4);
    gemm1_kernel<<<dim3(2, M / 128), 256, smem1>>>(x, b1, o);
    attf_kernel<<<nblk, 256, smemA>>>(gi, out);
}

// round 17
// speedup vs baseline: 1.1007x; 1.1007x over previous
#include <cuda_runtime.h>
#include <cstdint>
#include <cstddef>

// ---------------------------------------------------------------------------
// PolicyHead round 16 (= round 14 + reg-staged Mt prefetch + merged preps):
//   logits = out@M@out^T + u.out_i + v.out_j + s0,  M = W2^T W3 (precomputed)
//   attf v7: v5 with stage s+1 Mt prefetched into registers during compute(s)
//   (LDG latency hidden under mma; STS+sync replaces exposed CPA_WAIT).
//   prep_all: w1/M/v in one kernel -> 3 launches/call -> ncu slot 6 = attf.
// ---------------------------------------------------------------------------

#define HDIM 256
#define MROWS 262144
#define PSCALE 0.0625f

__device__ unsigned g_out[(size_t)MROWS * HDIM];
__device__ unsigned g_w1[HDIM * HDIM];     // tf32 bits, perm'd k
__device__ unsigned g_mt[HDIM * HDIM];     // Mt[c,a], tf32, perm on a
__device__ float    g_u[HDIM];             // perm-indexed
__device__ float    g_v[HDIM];             // perm-indexed
__device__ float    g_wp[4 * HDIM];        // perm-indexed
__device__ float    g_misc[8];             // [0]=s0, [1..4]=d0[p]

__device__ __forceinline__ unsigned f2tf(float f) {
    unsigned r;
    asm("cvt.rna.tf32.f32 %0, %1;" : "=r"(r) : "f"(f));
    return r;
}
__device__ __forceinline__ int perm(int c) {
    return (c & ~7) | ((c & 3) << 1) | ((c >> 2) & 1);
}
__device__ __forceinline__ void mma8(float* d, const unsigned* a, const unsigned* b) {
    asm volatile(
        "mma.sync.aligned.m16n8k8.row.col.f32.tf32.tf32.f32 "
        "{%0,%1,%2,%3}, {%4,%5,%6,%7}, {%8,%9}, {%0,%1,%2,%3};\n"
        : "+f"(d[0]), "+f"(d[1]), "+f"(d[2]), "+f"(d[3])
        : "r"(a[0]), "r"(a[1]), "r"(a[2]), "r"(a[3]), "r"(b[0]), "r"(b[1]));
}
__device__ __forceinline__ unsigned sptr(const void* p) {
    return (unsigned)__cvta_generic_to_shared(p);
}
__device__ __forceinline__ void cpa16(unsigned s, const void* g) {
    asm volatile("cp.async.ca.shared.global [%0], [%1], 16;" :: "r"(s), "l"(g));
}
#define CPA_COMMIT asm volatile("cp.async.commit_group;")
#define CPA_WAIT(n) asm volatile("cp.async.wait_group %0;" :: "n"(n))

// ---------------------------------------------------------------------------
// prep_all: blocks 0..255 = w1 convert; 256..271 = Mt tile; 272 = vectors.
// ---------------------------------------------------------------------------
__global__ __launch_bounds__(256)
void prep_all(const float* __restrict__ w1,
              const float* __restrict__ w2, const float* __restrict__ b2,
              const float* __restrict__ w3, const float* __restrict__ b3,
              const float* __restrict__ w4) {
    const int bid = blockIdx.x, tid = threadIdx.x;
    if (bid < 256) {
        int i = bid * 256 + tid;
        int row = i >> 8, col = i & 255;
        g_w1[row * HDIM + perm(col)] = f2tf(w1[i]);
    } else if (bid < 272) {
        extern __shared__ float s[];
        float* s2 = s;               // [256][68]
        float* s3 = s + 256 * 68;
        const int mb = bid - 256;
        const int a0 = (mb & 3) * 64, c0 = (mb >> 2) * 64;
        for (int j = tid; j < 256 * 16; j += 256) {
            int h = j >> 4, q4 = (j & 15) << 2;
            *(float4*)&s2[h * 68 + q4] = *(const float4*)(w2 + h * HDIM + a0 + q4);
            *(float4*)&s3[h * 68 + q4] = *(const float4*)(w3 + h * HDIM + c0 + q4);
        }
        __syncthreads();
        const int tx = tid & 15, ty = tid >> 4;
        float acc[4][4] = {};
        for (int h = 0; h < 256; h++) {
            float4 av = *(float4*)&s2[h * 68 + tx * 4];
            float4 cv = *(float4*)&s3[h * 68 + ty * 4];
            float aa[4] = {av.x, av.y, av.z, av.w};
            float cc[4] = {cv.x, cv.y, cv.z, cv.w};
#pragma unroll
            for (int i = 0; i < 4; i++)
#pragma unroll
                for (int j = 0; j < 4; j++) acc[i][j] += cc[i] * aa[j];
        }
#pragma unroll
        for (int i = 0; i < 4; i++)
#pragma unroll
            for (int j = 0; j < 4; j++)
                g_mt[(c0 + ty * 4 + i) * HDIM + perm(a0 + tx * 4 + j)] = f2tf(acc[i][j]);
    } else {
        int a = tid;
        float u = 0.f, v = 0.f, p0 = 0.f, p1 = 0.f, p2 = 0.f, p3 = 0.f;
        for (int h = 0; h < 256; h++) {
            float w2v = w2[h * HDIM + a], w3v = w3[h * HDIM + a];
            u += w2v * b3[h];
            v += b2[h] * w3v;
            p0 += w3v * w4[0 * HDIM + h];
            p1 += w3v * w4[1 * HDIM + h];
            p2 += w3v * w4[2 * HDIM + h];
            p3 += w3v * w4[3 * HDIM + h];
        }
        int pa = perm(a);
        g_u[pa] = u; g_v[pa] = v;
        g_wp[0 * HDIM + pa] = p0; g_wp[1 * HDIM + pa] = p1;
        g_wp[2 * HDIM + pa] = p2; g_wp[3 * HDIM + pa] = p3;
        if (a == 0) {
            float s = 0.f;
            for (int h = 0; h < 256; h++) s += b2[h] * b3[h];
            g_misc[0] = s;
        }
        if (a >= 1 && a <= 4) {
            float d = 0.f;
            for (int h = 0; h < 256; h++) d += b3[h] * w4[(a - 1) * HDIM + h];
            g_misc[a] = d;
        }
    }
}

// ---------------------------------------------------------------------------
// GEMM1 (round-5, proven 255us): out = relu(x @ W1^T + b1).
// ---------------------------------------------------------------------------
constexpr int GSA = 36;
constexpr int GSB = 40;

__global__ __launch_bounds__(256, 2)
void gemm1_kernel(const float* __restrict__ A, const float* __restrict__ bias,
                  unsigned* __restrict__ C) {
    extern __shared__ unsigned sh[];
    unsigned* sA = sh;
    unsigned* sB = sh + 2 * 128 * GSA;
    const int m0 = blockIdx.y * 128, n0 = blockIdx.x * 128;
    const int tid = threadIdx.x;
    const int warp = tid >> 5, lane = tid & 31, g = lane >> 2, t = lane & 3;
    const int wm = warp >> 1, wn = warp & 1;

    float acc[2][8][4];
#pragma unroll
    for (int i = 0; i < 2; i++)
#pragma unroll
        for (int j = 0; j < 8; j++)
#pragma unroll
            for (int l = 0; l < 4; l++) acc[i][j][l] = 0.f;

    const int lrow = tid >> 3, lc4 = (tid & 7) << 2;

#pragma unroll
    for (int i = 0; i < 4; i++) {
        int row = lrow + i * 32;
        cpa16(sptr(&sA[row * GSA + lc4]), A + (size_t)(m0 + row) * HDIM + lc4);
        cpa16(sptr(&sB[row * GSB + lc4]), g_w1 + (size_t)(n0 + row) * HDIM + lc4);
    }
    CPA_COMMIT;

    for (int c = 0; c < 8; c++) {
        int cur = c & 1;
        if (c < 7) {
            int nx = cur ^ 1, k0 = (c + 1) * 32;
#pragma unroll
            for (int i = 0; i < 4; i++) {
                int row = lrow + i * 32;
                cpa16(sptr(&sA[nx * 128 * GSA + row * GSA + lc4]),
                      A + (size_t)(m0 + row) * HDIM + k0 + lc4);
                cpa16(sptr(&sB[nx * 128 * GSB + row * GSB + lc4]),
                      g_w1 + (size_t)(n0 + row) * HDIM + k0 + lc4);
            }
            CPA_COMMIT;
            CPA_WAIT(1);
        } else {
            CPA_WAIT(0);
        }
        __syncthreads();
        const unsigned* As = &sA[cur * 128 * GSA];
        const unsigned* Bs = &sB[cur * 128 * GSB];
#pragma unroll
        for (int ks = 0; ks < 32; ks += 8) {
            unsigned a[2][4];
#pragma unroll
            for (int mi = 0; mi < 2; mi++) {
                int r = wm * 32 + mi * 16;
                a[mi][0] = f2tf(__uint_as_float(As[(r + g) * GSA + ks + t]));
                a[mi][1] = f2tf(__uint_as_float(As[(r + g + 8) * GSA + ks + t]));
                a[mi][2] = f2tf(__uint_as_float(As[(r + g) * GSA + ks + t + 4]));
                a[mi][3] = f2tf(__uint_as_float(As[(r + g + 8) * GSA + ks + t + 4]));
            }
#pragma unroll
            for (int ni = 0; ni < 8; ni++) {
                int cc = wn * 64 + ni * 8;
                uint2 bv = *(const uint2*)&Bs[(cc + g) * GSB + ks + 2 * t];
                unsigned bb[2] = {bv.x, bv.y};
                mma8(acc[0][ni], a[0], bb);
                mma8(acc[1][ni], a[1], bb);
            }
        }
        __syncthreads();
    }
#pragma unroll
    for (int mi = 0; mi < 2; mi++)
#pragma unroll
        for (int h = 0; h < 2; h++) {
            int r = m0 + wm * 32 + mi * 16 + g + h * 8;
#pragma unroll
            for (int ni = 0; ni < 8; ni++) {
                int cc = n0 + wn * 64 + ni * 8 + 2 * t;
                float v0 = fmaxf(acc[mi][ni][h * 2 + 0] + bias[cc], 0.f);
                float v1 = fmaxf(acc[mi][ni][h * 2 + 1] + bias[cc + 1], 0.f);
                C[(size_t)r * HDIM + perm(cc)]     = f2tf(v0);
                C[(size_t)r * HDIM + perm(cc + 1)] = f2tf(v1);
            }
        }
}

// ---------------------------------------------------------------------------
// attf v7: v5 with Mt stage s+1 prefetched into registers during compute(s).
// smem: outs[64x256 packed swz] | mt[256x32 packed swz] (qtmp alias) | misc.
// ---------------------------------------------------------------------------
constexpr int A4_OUTS  = 0;           // 64*256 = 16384 words
constexpr int A4_MT    = 16384;       // 256*32 = 8192 words (qtmp: 64*64 alias)
constexpr int A4_MISC  = 24576;       // uo64 + vo64 + offs32 = 160
constexpr int A4_WORDS = 24736;       // 98944 bytes

__global__ __launch_bounds__(256, 2)
void attf_kernel(const int* __restrict__ gidx, float* __restrict__ out) {
    extern __shared__ unsigned sh[];
    unsigned* outs = sh + A4_OUTS;
    unsigned* mt   = sh + A4_MT;
    unsigned* qtmp = mt;                     // alias: mt dead after phase 1
    float* uo   = (float*)(sh + A4_MISC);
    float* vo   = uo + 64;
    float* offs = vo + 64;
    float* fulls = (float*)sh;               // alias outs (dead after reads)

    const int b = blockIdx.x, tid = threadIdx.x;
    const unsigned* ob = g_out + (size_t)b * 64 * HDIM;

    // prologue: outs (packed+swizzled) + Mt stage 0 via cp.async
#pragma unroll
    for (int i = 0; i < 16; i++) {
        int idx = tid + i * 256;
        int row = idx >> 6, c4 = (idx & 63) << 2;
        cpa16(sptr(&outs[row * 256 + (c4 ^ ((row & 3) << 3))]),
              ob + (size_t)row * HDIM + c4);
    }
#pragma unroll
    for (int i = 0; i < 8; i++) {
        int e = tid + i * 256;
        int r = e >> 3, c4 = (e & 7) << 2;
        cpa16(sptr(&mt[r * 32 + (c4 ^ ((r & 3) << 3))]),
              g_mt + (size_t)r * HDIM + c4);
    }
    CPA_COMMIT;

    const int warp = tid >> 5, lane = tid & 31, g = lane >> 2, t = lane & 3;
    const int sw = (g & 3) << 3;
    const int wm = warp >> 2, wn = warp & 3;     // phase 1: 32x64 tiles
    const int wm2 = warp >> 1, wn2 = warp & 1;   // phase 2: 16x32 tiles
    const int prow = tid >> 3, pc4 = (tid & 7) << 2;   // prefetch indexing

    float acc[2][8][4];
#pragma unroll
    for (int i = 0; i < 2; i++)
#pragma unroll
        for (int j = 0; j < 8; j++)
#pragma unroll
            for (int l = 0; l < 4; l++) acc[i][j][l] = 0.f;

    CPA_WAIT(0);
    __syncthreads();      // outs + Mt stage 0 resident

    // ---- phase 1: tmp = outs @ Mt^T; next Mt stage prefetched to regs ----
    for (int s = 0; s < 8; s++) {
        uint4 pre[8];
        if (s < 7) {
            const int kn = (s + 1) * 32;
#pragma unroll
            for (int i = 0; i < 8; i++) {
                int r = prow + i * 32;
                pre[i] = *(const uint4*)(g_mt + (size_t)r * HDIM + kn + pc4);
            }
        }
        const int kb = s * 32;
#pragma unroll
        for (int ks = 0; ks < 32; ks += 8) {
            unsigned a[2][4];
#pragma unroll
            for (int mi = 0; mi < 2; mi++) {
                int r0 = wm * 32 + mi * 16 + g;
                uint2 a0 = *(const uint2*)&outs[r0 * 256 + ((kb + ks + 2 * t) ^ sw)];
                uint2 a1 = *(const uint2*)&outs[(r0 + 8) * 256 + ((kb + ks + 2 * t) ^ sw)];
                a[mi][0] = a0.x; a[mi][1] = a1.x; a[mi][2] = a0.y; a[mi][3] = a1.y;
            }
#pragma unroll
            for (int ni = 0; ni < 8; ni++) {
                int c = wn * 64 + ni * 8 + g;
                uint2 bv = *(const uint2*)&mt[c * 32 + ((ks + 2 * t) ^ sw)];
                unsigned bb[2] = {bv.x, bv.y};
                mma8(acc[0][ni], a[0], bb);
                mma8(acc[1][ni], a[1], bb);
            }
        }
        __syncthreads();       // all warps done reading stage s
        if (s < 7) {
#pragma unroll
            for (int i = 0; i < 8; i++) {
                int r = prow + i * 32;
                *(uint4*)&mt[r * 32 + (pc4 ^ ((r & 3) << 3))] = pre[i];
            }
            __syncthreads();   // stage s+1 visible
        }
    }

    // ---- phase 2: logits = tmp @ outs^T via 4 q-passes through qtmp ----
    float acc2[4][4];
#pragma unroll
    for (int i = 0; i < 4; i++)
#pragma unroll
        for (int j = 0; j < 4; j++) acc2[i][j] = 0.f;

    for (int q = 0; q < 4; q++) {
        __syncthreads();   // prior q reads (or phase-1 mt reads) complete
        if (wn == q) {
#pragma unroll
            for (int mi = 0; mi < 2; mi++)
#pragma unroll
                for (int ni = 0; ni < 8; ni++) {
                    int lc = ni * 8 + 2 * t;
                    int lp0 = (lc & ~7) | ((lc & 3) << 1) | ((lc >> 2) & 1);
                    int lc1 = lc + 1;
                    int lp1 = (lc1 & ~7) | ((lc1 & 3) << 1) | ((lc1 >> 2) & 1);
                    int r = wm * 32 + mi * 16 + g;
                    qtmp[r * 64 + (lp0 ^ sw)]       = f2tf(acc[mi][ni][0]);
                    qtmp[r * 64 + (lp1 ^ sw)]       = f2tf(acc[mi][ni][1]);
                    qtmp[(r + 8) * 64 + (lp0 ^ sw)] = f2tf(acc[mi][ni][2]);
                    qtmp[(r + 8) * 64 + (lp1 ^ sw)] = f2tf(acc[mi][ni][3]);
                }
        }
        __syncthreads();
#pragma unroll
        for (int k8 = 0; k8 < 64; k8 += 8) {
            int r2 = wm2 * 16 + g;
            uint2 a0 = *(const uint2*)&qtmp[r2 * 64 + ((k8 + 2 * t) ^ sw)];
            uint2 a1 = *(const uint2*)&qtmp[(r2 + 8) * 64 + ((k8 + 2 * t) ^ sw)];
            unsigned a[4] = {a0.x, a1.x, a0.y, a1.y};
#pragma unroll
            for (int ni = 0; ni < 4; ni++) {
                int c = wn2 * 32 + ni * 8 + g;
                uint2 bv = *(const uint2*)&outs[c * 256 + ((q * 64 + k8 + 2 * t) ^ sw)];
                unsigned bb[2] = {bv.x, bv.y};
                mma8(acc2[ni], a, bb);
            }
        }
    }

    // ---- rank-1 terms: one row per warp, lane-striped (conflict-free) ----
    {
#pragma unroll
        for (int rr = 0; rr < 8; rr++) {
            int r = warp * 8 + rr;
            int swr = (r & 3) << 3;
            const unsigned* orow = &outs[r * 256];
            float su = 0.f, sv = 0.f;
#pragma unroll
            for (int j = 0; j < 8; j++) {
                int pp = lane + 32 * j;
                float ov = __uint_as_float(orow[pp ^ swr]);
                su += g_u[pp] * ov;
                sv += g_v[pp] * ov;
            }
#pragma unroll
            for (int d = 16; d > 0; d >>= 1) {
                su += __shfl_down_sync(0xffffffffu, su, d);
                sv += __shfl_down_sync(0xffffffffu, sv, d);
            }
            if (lane == 0) { uo[r] = su; vo[r] = sv; }
        }
    }
    {
        int s = warp;
        int r = 56 + s, swr = (r & 3) << 3;
        const unsigned* kr = &outs[r * 256];
#pragma unroll
        for (int p = 0; p < 4; p++) {
            const float* wr = g_wp + p * HDIM;
            float sum = 0.f;
#pragma unroll
            for (int j = 0; j < 8; j++) {
                int pp = lane + 32 * j;
                sum += __uint_as_float(kr[pp ^ swr]) * wr[pp];
            }
#pragma unroll
            for (int d = 16; d > 0; d >>= 1)
                sum += __shfl_down_sync(0xffffffffu, sum, d);
            if (lane == 0) offs[p * 8 + s] = sum + g_misc[1 + p];
        }
    }
    __syncthreads();   // all outs reads done -> fulls may overwrite

    const float s0v = g_misc[0];
#pragma unroll
    for (int ni = 0; ni < 4; ni++) {
        int cc = wn2 * 32 + ni * 8 + 2 * t;
        int r = wm2 * 16 + g;
        fulls[r * 64 + cc]           = (acc2[ni][0] + uo[r] + vo[cc] + s0v) * PSCALE;
        fulls[r * 64 + cc + 1]       = (acc2[ni][1] + uo[r] + vo[cc + 1] + s0v) * PSCALE;
        fulls[(r + 8) * 64 + cc]     = (acc2[ni][2] + uo[r + 8] + vo[cc] + s0v) * PSCALE;
        fulls[(r + 8) * 64 + cc + 1] = (acc2[ni][3] + uo[r + 8] + vo[cc + 1] + s0v) * PSCALE;
    }
    __syncthreads();

    if (tid < 192) {
        int qq = tid / 24, rr = tid % 24, s = rr / 3, p = rr % 3;
        fulls[4096 + tid] = offs[p * 8 + s] + offs[24 + s]
                          + fulls[(48 + qq) * 64 + 56 + s];
    }
    __syncthreads();

    float* obp = out + (size_t)b * 1858;
    for (int i = tid; i < 1858; i += 256) obp[i] = fulls[gidx[i]];
}

// ---------------------------------------------------------------------------
extern "C" void kernel_launch(void* const* d_in, const int* in_sizes, int n_in,
                              void* d_out, int out_size) {
    const float* x  = (const float*)d_in[0];
    const float* w1 = (const float*)d_in[1];
    const float* b1 = (const float*)d_in[2];
    const float* w2 = (const float*)d_in[3];
    const float* b2 = (const float*)d_in[4];
    const float* w3 = (const float*)d_in[5];
    const float* b3 = (const float*)d_in[6];
    const float* w4 = (const float*)d_in[7];
    const int*   gi = (const int*)d_in[8];
    float* out = (float*)d_out;

    const int M = in_sizes[0] / HDIM;     // 262144
    const int nblk = M / 64;              // 4096

    unsigned* o;
    cudaGetSymbolAddress((void**)&o, g_out);

    const int smemP = 2 * 256 * 68 * 4;                        // 139264
    const int smem1 = (2 * 128 * GSA + 2 * 128 * GSB) * 4;     // 77824
    const int smemA = A4_WORDS * 4;                            // 98944

    static bool init = false;
    if (!init) {
        cudaFuncSetAttribute((const void*)prep_all,
                             cudaFuncAttributeMaxDynamicSharedMemorySize, smemP);
        cudaFuncSetAttribute((const void*)gemm1_kernel,
                             cudaFuncAttributeMaxDynamicSharedMemorySize, smem1);
        cudaFuncSetAttribute((const void*)attf_kernel,
                             cudaFuncAttributeMaxDynamicSharedMemorySize, smemA);
        init = true;
    }

    prep_all<<<273, 256, smemP>>>(w1, w2, b2, w3, b3, w4);
    gemm1_kernel<<<dim3(2, M / 128), 256, smem1>>>(x, b1, o);
    attf_kernel<<<nblk, 256, smemA>>>(gi, out);
}